// round 1
// baseline (speedup 1.0000x reference)
#include <cuda_runtime.h>

// QAEEncoder: 10-qubit statevector sim, B states, fused circuit:
//  stage A: per-qubit RZ(w[10+q])*RY(w[q])
//  CNOT ring (bit-linear permutation)
//  stage B: per-qubit RZ(w[40+q])*RY(w[20+q]+w[30+q])
//  CNOT ring
//  stage C: per-qubit RY(w[50+q])
//  then Pauli X/Y/Z expectations on qubits 0..5.
// Qubit q <-> flat amplitude bit (9-q)  (row-major reshape).

constexpr int AMP = 1024;
constexpr int TPS = 64;    // threads per state
constexpr int SPB = 4;     // states per block
constexpr int NT  = TPS * SPB;

// Composed gather map for the 10-CNOT ring:
// new[i] = old[g(i)],  g(i) = (i ^ (i>>1)) ^ ((i&1) ? 0x300 : 0)
__device__ __forceinline__ int cnot_gather(int i) {
    return (i ^ (i >> 1)) ^ ((i & 1) ? 0x300 : 0);
}

__device__ __forceinline__ float warp_sum(float v) {
#pragma unroll
    for (int o = 16; o; o >>= 1) v += __shfl_xor_sync(0xffffffffu, v, o);
    return v;
}

__global__ void __launch_bounds__(NT)
qae_kernel(const float* __restrict__ x,
           const float* __restrict__ w,
           float* __restrict__ out,
           int B, int D)
{
    __shared__ float2 st[SPB * AMP];     // 32 KB statevectors
    __shared__ float4 gates[30];         // (cos, sin, e_r, e_i) per fused gate
    __shared__ float  acc[SPB * 18];
    __shared__ float  snorm[SPB];

    const int tid = threadIdx.x;
    const int s   = tid / TPS;
    const int lt  = tid % TPS;
    const int b   = blockIdx.x * SPB + s;
    const bool active = (b < B);
    float2* S = st + s * AMP;

    // Build fused gate table (once per block).
    if (tid < 30) {
        int stage = tid / 10, q = tid - stage * 10;
        float theta, phi;
        if (stage == 0)      { theta = w[q];               phi = w[10 + q]; }
        else if (stage == 1) { theta = w[20 + q] + w[30 + q]; phi = w[40 + q]; }
        else                 { theta = w[50 + q];          phi = 0.0f; }
        float c, sn, er, ei;
        sincosf(0.5f * theta, &sn, &c);
        sincosf(0.5f * phi,  &ei, &er);
        gates[tid] = make_float4(c, sn, er, ei);
    }
    if (tid < SPB * 18) acc[tid]  = 0.0f;
    if (tid < SPB)      snorm[tid] = 0.0f;
    __syncthreads();

    // Load input row (pad 768 -> 1024), accumulate squared norm.
    {
        float ss = 0.0f;
#pragma unroll
        for (int k = 0; k < AMP / TPS; k++) {
            int idx = lt + k * TPS;
            float v = (active && idx < D) ? x[(size_t)b * D + idx] : 0.0f;
            S[idx] = make_float2(v, 0.0f);
            ss += v * v;
        }
        ss = warp_sum(ss);
        if ((tid & 31) == 0) atomicAdd(&snorm[s], ss);
    }
    __syncthreads();
    {
        float inv = 1.0f / fmaxf(sqrtf(snorm[s]), 1e-8f);
#pragma unroll
        for (int k = 0; k < AMP / TPS; k++)
            S[lt + k * TPS].x *= inv;
    }
    __syncthreads();

    // 3 stages of 10 fused 1-qubit gates, CNOT-ring permutation between stages.
#pragma unroll 1
    for (int stage = 0; stage < 3; stage++) {
#pragma unroll 1
        for (int q = 0; q < 10; q++) {
            const float4 g = gates[stage * 10 + q];
            const float c = g.x, sn = g.y, er = g.z, ei = g.w;
            const int p    = 9 - q;
            const int bitp = 1 << p;
            const int mask = bitp - 1;
#pragma unroll
            for (int k = 0; k < 512 / TPS; k++) {
                int m  = lt + k * TPS;
                int i0 = ((m & ~mask) << 1) | (m & mask);
                int i1 = i0 | bitp;
                float2 a  = S[i0];
                float2 bb = S[i1];
                // t0 = c*a - s*b ; t1 = s*a + c*b   (real coefficients)
                float t0r = c * a.x - sn * bb.x;
                float t0i = c * a.y - sn * bb.y;
                float t1r = sn * a.x + c * bb.x;
                float t1i = sn * a.y + c * bb.y;
                // a' = conj(e)*t0 ; b' = e*t1  with e = e^{+i phi/2}
                S[i0] = make_float2(er * t0r + ei * t0i, er * t0i - ei * t0r);
                S[i1] = make_float2(er * t1r - ei * t1i, er * t1i + ei * t1r);
            }
            __syncthreads();
        }
        if (stage < 2) {
            float2 v[AMP / TPS];
#pragma unroll
            for (int k = 0; k < AMP / TPS; k++)
                v[k] = S[cnot_gather(lt + k * TPS)];
            __syncthreads();
#pragma unroll
            for (int k = 0; k < AMP / TPS; k++)
                S[lt + k * TPS] = v[k];
            __syncthreads();
        }
    }

    // Expectation values: X_q = 2*sum Re(conj(a0)a1), Y_q = 2*sum Im, Z_q = sum |a0|^2-|a1|^2
#pragma unroll 1
    for (int q = 0; q < 6; q++) {
        const int p    = 9 - q;
        const int bitp = 1 << p;
        const int mask = bitp - 1;
        float xs = 0.0f, ys = 0.0f, zs = 0.0f;
#pragma unroll
        for (int k = 0; k < 512 / TPS; k++) {
            int m  = lt + k * TPS;
            int i0 = ((m & ~mask) << 1) | (m & mask);
            float2 a0 = S[i0];
            float2 a1 = S[i0 | bitp];
            xs += a0.x * a1.x + a0.y * a1.y;
            ys += a0.x * a1.y - a0.y * a1.x;
            zs += (a0.x * a0.x + a0.y * a0.y) - (a1.x * a1.x + a1.y * a1.y);
        }
        xs = warp_sum(xs); ys = warp_sum(ys); zs = warp_sum(zs);
        if ((tid & 31) == 0) {
            atomicAdd(&acc[s * 18 + q],      2.0f * xs);
            atomicAdd(&acc[s * 18 + 6 + q],  2.0f * ys);
            atomicAdd(&acc[s * 18 + 12 + q], zs);
        }
    }
    __syncthreads();
    if (active && lt < 18)
        out[(size_t)b * 18 + lt] = acc[s * 18 + lt];
}

extern "C" void kernel_launch(void* const* d_in, const int* in_sizes, int n_in,
                              void* d_out, int out_size)
{
    int ix = 0, iw = 1;
    if (n_in >= 2 && in_sizes[0] < in_sizes[1]) { ix = 1; iw = 0; }
    const float* x = (const float*)d_in[ix];
    const float* w = (const float*)d_in[iw];
    float* out = (float*)d_out;

    int B = out_size / 18;
    int D = (B > 0) ? (in_sizes[ix] / B) : 0;

    int grid = (B + SPB - 1) / SPB;
    qae_kernel<<<grid, NT>>>(x, w, out, B, D);
}

// round 3
// speedup vs baseline: 3.4873x; 3.4873x over previous
#include <cuda_runtime.h>

// QAEEncoder, register-resident warp-per-state version.
// Circuit fused as:
//   stage A: RY(w[q]) real  -> CNOT ring -> attach permuted RZ(w[10+q]) phases
//   stage B: RY(w[20+q]+w[30+q]) complex -> CNOT ring -> attach permuted RZ(w[40+q]) phases
//   stage C: RY(w[50+q]) folded into expectation values (qubits 6..9 dropped:
//            they cannot affect the reduced state of measured qubits 0..5).
// Amplitude index i (10 bits): qubit q <-> bit p = 9-q.
// Thread layout: j = i[9:5] (32 register slots), lane = i[4:0].
// CNOT-ring composite permutation: new[i] = old[g(i)],
//   g(i) = (i ^ (i>>1)) ^ ((i&1) ? 0x300 : 0)   (validated in R1).

constexpr int SPB = 4;               // states (warps) per block
constexpr int NT  = 32 * SPB;

__device__ __forceinline__ float wsum(float v) {
#pragma unroll
    for (int o = 16; o; o >>= 1) v += __shfl_xor_sync(0xffffffffu, v, o);
    return v;
}

__global__ void __launch_bounds__(NT)
qae2_kernel(const float* __restrict__ x,
            const float* __restrict__ w,
            float* __restrict__ out,
            int B, int D)
{
    __shared__ float2 sstate[SPB * 1024];            // 32 KB: CNOT staging
    __shared__ float2 FA[64], GA[64], FB[64], GB[64]; // phase tables
    __shared__ float2 gAB[20];                        // (cos,sin) half-angle, stages A,B
    __shared__ float2 gC[6];                          // (cos,sin) full angle, stage C

    const int tid  = threadIdx.x;
    const int wid  = tid >> 5;
    const int lane = tid & 31;
    const int b    = blockIdx.x * SPB + wid;

    // ---- per-block tables --------------------------------------------------
    // Phase tables: phi'(i) = phi(g(i)) is affine in the bits of i and splits:
    //   F[j][l0]  covers bits p=5..9 of g(i)  (depends on j and lane bit0)
    //   G[lane][j0] covers bits p=0..4       (depends on lane and j bit0)
    for (int e = tid; e < 256; e += NT) {
        int tab = e >> 6, t = e & 63;
        int hi = t >> 1, lo = t & 1;
        int base = (tab >= 2) ? 40 : 10;
        float ph = 0.0f;
        if ((tab & 1) == 0) {   // F table: hi = j, lo = lane bit0
            int j = hi;
            int m5 = (j ^ (j >> 1)) & 1;
            int m6 = ((j >> 1) ^ (j >> 2)) & 1;
            int m7 = ((j >> 2) ^ (j >> 3)) & 1;
            int m8 = ((j >> 3) ^ (j >> 4) ^ lo) & 1;
            int m9 = ((j >> 4) ^ lo) & 1;
            ph  = w[base + 4] * (m5 ? 0.5f : -0.5f);
            ph += w[base + 3] * (m6 ? 0.5f : -0.5f);
            ph += w[base + 2] * (m7 ? 0.5f : -0.5f);
            ph += w[base + 1] * (m8 ? 0.5f : -0.5f);
            ph += w[base + 0] * (m9 ? 0.5f : -0.5f);
        } else {                // G table: hi = lane, lo = j bit0
            int l = hi;
            int m0 = (l ^ (l >> 1)) & 1;
            int m1 = ((l >> 1) ^ (l >> 2)) & 1;
            int m2 = ((l >> 2) ^ (l >> 3)) & 1;
            int m3 = ((l >> 3) ^ (l >> 4)) & 1;
            int m4 = ((l >> 4) ^ lo) & 1;
            ph  = w[base + 9] * (m0 ? 0.5f : -0.5f);
            ph += w[base + 8] * (m1 ? 0.5f : -0.5f);
            ph += w[base + 7] * (m2 ? 0.5f : -0.5f);
            ph += w[base + 6] * (m3 ? 0.5f : -0.5f);
            ph += w[base + 5] * (m4 ? 0.5f : -0.5f);
        }
        float c, s; sincosf(ph, &s, &c);
        float2 v = make_float2(c, s);
        if (tab == 0) FA[t] = v; else if (tab == 1) GA[t] = v;
        else if (tab == 2) FB[t] = v; else GB[t] = v;
    }
    if (tid < 20) {
        int st = tid / 10, q = tid % 10;
        float th = st ? (w[20 + q] + w[30 + q]) : w[q];
        float c, s; sincosf(0.5f * th, &s, &c);
        gAB[tid] = make_float2(c, s);
    }
    if (tid < 6) {
        float c, s; sincosf(w[50 + tid], &s, &c);
        gC[tid] = make_float2(c, s);
    }
    __syncthreads();
    if (b >= B) return;     // whole warp exits; remaining sync is warp-local

    float X[32], Y[32];

    // ---- load + normalize (state is real) ----------------------------------
    float ss = 0.0f;
#pragma unroll
    for (int j = 0; j < 32; j++) {
        int idx = (j << 5) | lane;
        float v = (idx < D) ? x[(size_t)b * D + idx] : 0.0f;
        X[j] = v; ss += v * v;
    }
    ss = wsum(ss);
    float inv = 1.0f / fmaxf(sqrtf(ss), 1e-8f);
#pragma unroll
    for (int j = 0; j < 32; j++) X[j] *= inv;

    // ---- stage A: 10 real RY gates ----------------------------------------
#pragma unroll
    for (int bl = 0; bl < 5; bl++) {            // local bits 5..9, qubit 4-bl
        float2 g = gAB[4 - bl];
        float c = g.x, s = g.y;
        int m = 1 << bl;
#pragma unroll
        for (int j = 0; j < 32; j++) if (!(j & m)) {
            float a = X[j], bb = X[j | m];
            X[j]     = c * a - s * bb;
            X[j | m] = s * a + c * bb;
        }
    }
#pragma unroll
    for (int pb = 0; pb < 5; pb++) {            // lane bits 0..4, qubit 9-pb
        float2 g = gAB[9 - pb];
        float c = g.x;
        float sgn = (lane & (1 << pb)) ? g.y : -g.y;
#pragma unroll
        for (int j = 0; j < 32; j++) {
            float part = __shfl_xor_sync(0xffffffffu, X[j], 1 << pb);
            X[j] = fmaf(sgn, part, c * X[j]);
        }
    }

    // ---- CNOT ring #1 (real, via shared) + attach phase A ------------------
    const int par = lane & 1;
    {
        float* shf = (float*)(sstate + wid * 1024);
#pragma unroll
        for (int j = 0; j < 32; j++) shf[(j << 5) | lane] = X[j];
        __syncwarp();
        float2 ga0 = GA[lane * 2], ga1 = GA[lane * 2 + 1];
#pragma unroll
        for (int j = 0; j < 32; j++) {
            int i  = (j << 5) | lane;
            int sp = (i ^ (i >> 1)) ^ (par ? 0x300 : 0);
            float r = shf[sp];
            float2 f = FA[j * 2 + par];
            float2 g = (j & 1) ? ga1 : ga0;
            float pr = f.x * g.x - f.y * g.y;
            float pi = f.x * g.y + f.y * g.x;
            X[j] = r * pr;
            Y[j] = r * pi;
        }
        __syncwarp();
    }

    // ---- stage B: 10 complex RY gates --------------------------------------
#pragma unroll
    for (int bl = 0; bl < 5; bl++) {
        float2 g = gAB[10 + 4 - bl];
        float c = g.x, s = g.y;
        int m = 1 << bl;
#pragma unroll
        for (int j = 0; j < 32; j++) if (!(j & m)) {
            float ax = X[j], ay = Y[j], bx = X[j | m], by = Y[j | m];
            X[j]     = c * ax - s * bx;  Y[j]     = c * ay - s * by;
            X[j | m] = s * ax + c * bx;  Y[j | m] = s * ay + c * by;
        }
    }
#pragma unroll
    for (int pb = 0; pb < 5; pb++) {
        float2 g = gAB[10 + 9 - pb];
        float c = g.x;
        float sgn = (lane & (1 << pb)) ? g.y : -g.y;
#pragma unroll
        for (int j = 0; j < 32; j++) {
            float px = __shfl_xor_sync(0xffffffffu, X[j], 1 << pb);
            float py = __shfl_xor_sync(0xffffffffu, Y[j], 1 << pb);
            X[j] = fmaf(sgn, px, c * X[j]);
            Y[j] = fmaf(sgn, py, c * Y[j]);
        }
    }

    // ---- CNOT ring #2 (complex, via shared) + attach phase B ---------------
    {
        float2* sh2 = sstate + wid * 1024;
#pragma unroll
        for (int j = 0; j < 32; j++) sh2[(j << 5) | lane] = make_float2(X[j], Y[j]);
        __syncwarp();
        float2 gb0 = GB[lane * 2], gb1 = GB[lane * 2 + 1];
#pragma unroll
        for (int j = 0; j < 32; j++) {
            int i  = (j << 5) | lane;
            int sp = (i ^ (i >> 1)) ^ (par ? 0x300 : 0);
            float2 v = sh2[sp];
            float2 f = FB[j * 2 + par];
            float2 g = (j & 1) ? gb1 : gb0;
            float pr = f.x * g.x - f.y * g.y;
            float pi = f.x * g.y + f.y * g.x;
            X[j] = v.x * pr - v.y * pi;
            Y[j] = v.x * pi + v.y * pr;
        }
    }

    // ---- expectation values (pre-stage-C), stage C folded in ---------------
    float zq[6] = {0, 0, 0, 0, 0, 0};
#pragma unroll
    for (int j = 0; j < 32; j++) {
        float nv = X[j] * X[j] + Y[j] * Y[j];
        zq[0] += (j & 16) ? -nv : nv;
        zq[1] += (j & 8)  ? -nv : nv;
        zq[2] += (j & 4)  ? -nv : nv;
        zq[3] += (j & 2)  ? -nv : nv;
        zq[4] += (j & 1)  ? -nv : nv;
        zq[5] += nv;
    }
    if (lane & 16) zq[5] = -zq[5];

    float xr[6], yi[6];
#pragma unroll
    for (int q = 0; q < 5; q++) {               // local measured qubits 0..4
        int m = 1 << (4 - q);
        float xa = 0.0f, ya = 0.0f;
#pragma unroll
        for (int j = 0; j < 32; j++) if (!(j & m)) {
            float ax = X[j], ay = Y[j], bx = X[j | m], by = Y[j | m];
            xa += ax * bx + ay * by;
            ya += ax * by - ay * bx;
        }
        xr[q] = 2.0f * xa;
        yi[q] = 2.0f * ya;
    }
    {                                            // qubit 5 = lane bit 4
        float x5 = 0.0f, y5 = 0.0f;
#pragma unroll
        for (int j = 0; j < 32; j++) {
            float px = __shfl_xor_sync(0xffffffffu, X[j], 16);
            float py = __shfl_xor_sync(0xffffffffu, Y[j], 16);
            x5 += X[j] * px + Y[j] * py;
            y5 += X[j] * py - Y[j] * px;
        }
        if (lane & 16) y5 = -y5;
        xr[5] = x5;                               // already counts both halves
        yi[5] = y5;
    }

#pragma unroll
    for (int q = 0; q < 6; q++) {
        xr[q] = wsum(xr[q]);
        yi[q] = wsum(yi[q]);
        zq[q] = wsum(zq[q]);
    }

    if (lane == 0) {
        float* o = out + (size_t)b * 18;
#pragma unroll
        for (int q = 0; q < 6; q++) {
            float c = gC[q].x, s = gC[q].y;
            // RY(th)^dag X RY(th) = c X + s Z ;  Z -> c Z - s X ;  Y -> Y
            o[q]      = c * xr[q] + s * zq[q];
            o[6 + q]  = yi[q];
            o[12 + q] = c * zq[q] - s * xr[q];
        }
    }
}

extern "C" void kernel_launch(void* const* d_in, const int* in_sizes, int n_in,
                              void* d_out, int out_size)
{
    int ix = 0, iw = 1;
    if (n_in >= 2 && in_sizes[0] < in_sizes[1]) { ix = 1; iw = 0; }
    const float* x = (const float*)d_in[ix];
    const float* w = (const float*)d_in[iw];
    float* out = (float*)d_out;

    int B = out_size / 18;
    int D = (B > 0) ? (in_sizes[ix] / B) : 0;

    int grid = (B + SPB - 1) / SPB;
    qae2_kernel<<<grid, NT>>>(x, w, out, B, D);
}

// round 4
// speedup vs baseline: 4.0747x; 1.1684x over previous
#include <cuda_runtime.h>

// QAEEncoder R4: register-resident warp-per-state, zero gate shuffles.
// Layouts over amp index i[9:0] (qubit q <-> bit p=9-q):
//   L0: lane=i[4:0], reg j=i[9:5]     L1: lane=i[9:5], reg j=i[4:0]
// Pipeline:
//   load+norm (L0, real) -> A gates q0-4 (L0 regs) -> T_A (L0->L1)
//   -> A gates q5-9 (L1 regs) -> C1 gather+phaseA (L1->L1, real->packed cplx)
//   -> B gates q5-9 (L1 regs, f32x2) -> T_B (L1->L0, 64-bit)
//   -> B gates q0-4 (L0 regs, f32x2) -> C2 gather+phaseB (L0->L0, unpack)
//   -> expvals with stage-C RY folded into (X,Z) rotation; qubits 6-9 traced out.
// CNOT-ring composite: new[i] = old[g(i)], g(i)=(i^(i>>1))^((i&1)?0x300:0).
// Shared staging padded stride 33 to kill transpose bank conflicts.

constexpr int SPB = 4;               // states (warps) per block
constexpr int NT  = 32 * SPB;
using u64 = unsigned long long;

__device__ __forceinline__ u64 pk2(float a, float b) {
    u64 r; asm("mov.b64 %0,{%1,%2};" : "=l"(r) : "f"(a), "f"(b)); return r;
}
__device__ __forceinline__ void upk2(u64 v, float& a, float& b) {
    asm("mov.b64 {%0,%1},%2;" : "=f"(a), "=f"(b) : "l"(v));
}
__device__ __forceinline__ u64 mul2(u64 a, u64 b) {
    u64 d; asm("mul.rn.f32x2 %0,%1,%2;" : "=l"(d) : "l"(a), "l"(b)); return d;
}
__device__ __forceinline__ u64 fma2(u64 a, u64 b, u64 c) {
    u64 d; asm("fma.rn.f32x2 %0,%1,%2,%3;" : "=l"(d) : "l"(a), "l"(b), "l"(c)); return d;
}
__device__ __forceinline__ float wsum(float v) {
#pragma unroll
    for (int o = 16; o; o >>= 1) v += __shfl_xor_sync(0xffffffffu, v, o);
    return v;
}

__global__ void __launch_bounds__(NT)
qae4_kernel(const float* __restrict__ x,
            const float* __restrict__ w,
            float* __restrict__ out,
            int B, int D)
{
    __shared__ u64    sbuf[SPB][33 * 32];             // 33.8 KB staging (aliased)
    __shared__ float2 FA[64], GA[64], FB[64], GB[64]; // phase tables
    __shared__ float2 gAB[20];                        // half-angle (c,s) stages A,B
    __shared__ float2 gC[6];                          // full-angle (c,s) stage C

    const int tid  = threadIdx.x;
    const int wid  = tid >> 5;
    const int lane = tid & 31;
    const int b    = blockIdx.x * SPB + wid;

    // ---- per-block tables (identical construction to R3) -------------------
    for (int e = tid; e < 256; e += NT) {
        int tab = e >> 6, t = e & 63;
        int hi = t >> 1, lo = t & 1;
        int base = (tab >= 2) ? 40 : 10;
        float ph;
        if ((tab & 1) == 0) {   // F: keyed by i[9:5] (hi) and i0 (lo)
            int j = hi;
            int m5 = (j ^ (j >> 1)) & 1;
            int m6 = ((j >> 1) ^ (j >> 2)) & 1;
            int m7 = ((j >> 2) ^ (j >> 3)) & 1;
            int m8 = ((j >> 3) ^ (j >> 4) ^ lo) & 1;
            int m9 = ((j >> 4) ^ lo) & 1;
            ph  = w[base + 4] * (m5 ? 0.5f : -0.5f);
            ph += w[base + 3] * (m6 ? 0.5f : -0.5f);
            ph += w[base + 2] * (m7 ? 0.5f : -0.5f);
            ph += w[base + 1] * (m8 ? 0.5f : -0.5f);
            ph += w[base + 0] * (m9 ? 0.5f : -0.5f);
        } else {                // G: keyed by i[4:0] (hi) and i5 (lo)
            int l = hi;
            int m0 = (l ^ (l >> 1)) & 1;
            int m1 = ((l >> 1) ^ (l >> 2)) & 1;
            int m2 = ((l >> 2) ^ (l >> 3)) & 1;
            int m3 = ((l >> 3) ^ (l >> 4)) & 1;
            int m4 = ((l >> 4) ^ lo) & 1;
            ph  = w[base + 9] * (m0 ? 0.5f : -0.5f);
            ph += w[base + 8] * (m1 ? 0.5f : -0.5f);
            ph += w[base + 7] * (m2 ? 0.5f : -0.5f);
            ph += w[base + 6] * (m3 ? 0.5f : -0.5f);
            ph += w[base + 5] * (m4 ? 0.5f : -0.5f);
        }
        float c, s; sincosf(ph, &s, &c);
        float2 v = make_float2(c, s);
        if (tab == 0) FA[t] = v; else if (tab == 1) GA[t] = v;
        else if (tab == 2) FB[t] = v; else GB[t] = v;
    }
    if (tid < 20) {
        int st = tid / 10, q = tid % 10;
        float th = st ? (w[20 + q] + w[30 + q]) : w[q];
        float c, s; sincosf(0.5f * th, &s, &c);
        gAB[tid] = make_float2(c, s);
    }
    if (tid < 6) {
        float c, s; sincosf(w[50 + tid], &s, &c);
        gC[tid] = make_float2(c, s);
    }
    __syncthreads();
    if (b >= B) return;                 // whole-warp exit; remaining sync warp-local

    float* bufr = (float*)sbuf[wid];    // real staging view (stride 33)
    u64*   bufu = sbuf[wid];            // packed complex view (stride 33)

    float X[32], Y[32];

    // ---- load + normalize (L0, real) ---------------------------------------
    float ss = 0.0f;
#pragma unroll
    for (int j = 0; j < 32; j++) {
        int idx = (j << 5) | lane;
        float v = (idx < D) ? x[(size_t)b * D + idx] : 0.0f;
        X[j] = v; ss += v * v;
    }
    ss = wsum(ss);
    float inv = 1.0f / fmaxf(sqrtf(ss), 1e-8f);
#pragma unroll
    for (int j = 0; j < 32; j++) X[j] *= inv;

    // ---- stage A gates, qubits 0-4 (L0 register bits) ----------------------
#pragma unroll
    for (int bl = 0; bl < 5; bl++) {
        float2 g = gAB[4 - bl];
        float c = g.x, s = g.y;
        int m = 1 << bl;
#pragma unroll
        for (int j = 0; j < 32; j++) if (!(j & m)) {
            float a = X[j], bb = X[j | m];
            X[j]     = c * a - s * bb;
            X[j | m] = s * a + c * bb;
        }
    }

    // ---- T_A: transpose L0 -> L1 (real) ------------------------------------
#pragma unroll
    for (int j = 0; j < 32; j++) bufr[lane * 33 + j] = X[j];
    __syncwarp();
#pragma unroll
    for (int j = 0; j < 32; j++) X[j] = bufr[j * 33 + lane];
    __syncwarp();

    // ---- stage A gates, qubits 5-9 (L1 register bits) ----------------------
#pragma unroll
    for (int bl = 0; bl < 5; bl++) {
        float2 g = gAB[9 - bl];
        float c = g.x, s = g.y;
        int m = 1 << bl;
#pragma unroll
        for (int j = 0; j < 32; j++) if (!(j & m)) {
            float a = X[j], bb = X[j | m];
            X[j]     = c * a - s * bb;
            X[j | m] = s * a + c * bb;
        }
    }

    // ---- C1: CNOT gather + phase A (L1 -> L1, real -> packed complex) ------
    u64 P[32];
    {
#pragma unroll
        for (int j = 0; j < 32; j++) bufr[lane * 33 + j] = X[j];
        __syncwarp();
        float2 f0 = FA[lane * 2], f1 = FA[lane * 2 + 1];
#pragma unroll
        for (int j = 0; j < 32; j++) {
            int i  = (lane << 5) | j;
            int gi = (i ^ (i >> 1)) ^ ((j & 1) ? 0x300 : 0);
            float r = bufr[(gi >> 5) * 33 + (gi & 31)];
            float2 f = (j & 1) ? f1 : f0;
            float2 g = GA[j * 2 + (lane & 1)];
            float pr = f.x * g.x - f.y * g.y;
            float pi = f.x * g.y + f.y * g.x;
            P[j] = mul2(pk2(r, r), pk2(pr, pi));
        }
        __syncwarp();
    }

    // ---- stage B gates, qubits 5-9 (L1 register bits, f32x2) ---------------
#pragma unroll
    for (int bl = 0; bl < 5; bl++) {
        float2 g = gAB[10 + 9 - bl];
        u64 cc = pk2(g.x, g.x), sp = pk2(g.y, g.y), sn = pk2(-g.y, -g.y);
        int m = 1 << bl;
#pragma unroll
        for (int j = 0; j < 32; j++) if (!(j & m)) {
            u64 a = P[j], bb = P[j | m];
            P[j]     = fma2(bb, sn, mul2(a, cc));
            P[j | m] = fma2(a, sp, mul2(bb, cc));
        }
    }

    // ---- T_B: transpose L1 -> L0 (packed complex) --------------------------
#pragma unroll
    for (int j = 0; j < 32; j++) bufu[lane * 33 + j] = P[j];
    __syncwarp();
#pragma unroll
    for (int j = 0; j < 32; j++) P[j] = bufu[j * 33 + lane];
    __syncwarp();

    // ---- stage B gates, qubits 0-4 (L0 register bits, f32x2) ---------------
#pragma unroll
    for (int bl = 0; bl < 5; bl++) {
        float2 g = gAB[10 + 4 - bl];
        u64 cc = pk2(g.x, g.x), sp = pk2(g.y, g.y), sn = pk2(-g.y, -g.y);
        int m = 1 << bl;
#pragma unroll
        for (int j = 0; j < 32; j++) if (!(j & m)) {
            u64 a = P[j], bb = P[j | m];
            P[j]     = fma2(bb, sn, mul2(a, cc));
            P[j | m] = fma2(a, sp, mul2(bb, cc));
        }
    }

    // ---- C2: CNOT gather + phase B (L0 -> L0, unpack to X,Y) ---------------
    {
#pragma unroll
        for (int j = 0; j < 32; j++) bufu[lane * 33 + j] = P[j];
        __syncwarp();
        float2 g0 = GB[lane * 2], g1 = GB[lane * 2 + 1];
#pragma unroll
        for (int j = 0; j < 32; j++) {
            int i  = (j << 5) | lane;
            int gi = (i ^ (i >> 1)) ^ ((lane & 1) ? 0x300 : 0);
            u64 v = bufu[(gi & 31) * 33 + (gi >> 5)];
            float vx, vy; upk2(v, vx, vy);
            float2 f = FB[j * 2 + (lane & 1)];
            float2 g = (j & 1) ? g1 : g0;
            float pr = f.x * g.x - f.y * g.y;
            float pi = f.x * g.y + f.y * g.x;
            X[j] = vx * pr - vy * pi;
            Y[j] = vx * pi + vy * pr;
        }
    }

    // ---- expectation values (L0), stage C folded ---------------------------
    float zq[6] = {0, 0, 0, 0, 0, 0};
#pragma unroll
    for (int j = 0; j < 32; j++) {
        float nv = X[j] * X[j] + Y[j] * Y[j];
        zq[0] += (j & 16) ? -nv : nv;
        zq[1] += (j & 8)  ? -nv : nv;
        zq[2] += (j & 4)  ? -nv : nv;
        zq[3] += (j & 2)  ? -nv : nv;
        zq[4] += (j & 1)  ? -nv : nv;
        zq[5] += nv;
    }
    if (lane & 16) zq[5] = -zq[5];

    float xr[6], yi[6];
#pragma unroll
    for (int q = 0; q < 5; q++) {               // measured qubits 0..4 (j bits)
        int m = 1 << (4 - q);
        float xa = 0.0f, ya = 0.0f;
#pragma unroll
        for (int j = 0; j < 32; j++) if (!(j & m)) {
            float ax = X[j], ay = Y[j], bx = X[j | m], by = Y[j | m];
            xa += ax * bx + ay * by;
            ya += ax * by - ay * bx;
        }
        xr[q] = 2.0f * xa;
        yi[q] = 2.0f * ya;
    }
    {                                            // qubit 5 = lane bit 4
        float x5 = 0.0f, y5 = 0.0f;
#pragma unroll
        for (int j = 0; j < 32; j++) {
            float px = __shfl_xor_sync(0xffffffffu, X[j], 16);
            float py = __shfl_xor_sync(0xffffffffu, Y[j], 16);
            x5 += X[j] * px + Y[j] * py;
            y5 += X[j] * py - Y[j] * px;
        }
        if (lane & 16) y5 = -y5;
        xr[5] = x5;
        yi[5] = y5;
    }

#pragma unroll
    for (int q = 0; q < 6; q++) {
        xr[q] = wsum(xr[q]);
        yi[q] = wsum(yi[q]);
        zq[q] = wsum(zq[q]);
    }

    if (lane == 0) {
        float* o = out + (size_t)b * 18;
#pragma unroll
        for (int q = 0; q < 6; q++) {
            float c = gC[q].x, s = gC[q].y;
            o[q]      = c * xr[q] + s * zq[q];
            o[6 + q]  = yi[q];
            o[12 + q] = c * zq[q] - s * xr[q];
        }
    }
}

extern "C" void kernel_launch(void* const* d_in, const int* in_sizes, int n_in,
                              void* d_out, int out_size)
{
    int ix = 0, iw = 1;
    if (n_in >= 2 && in_sizes[0] < in_sizes[1]) { ix = 1; iw = 0; }
    const float* x = (const float*)d_in[ix];
    const float* w = (const float*)d_in[iw];
    float* out = (float*)d_out;

    int B = out_size / 18;
    int D = (B > 0) ? (in_sizes[ix] / B) : 0;

    int grid = (B + SPB - 1) / SPB;
    qae4_kernel<<<grid, NT>>>(x, w, out, B, D);
}

// round 5
// speedup vs baseline: 4.3116x; 1.0581x over previous
#include <cuda_runtime.h>

// QAEEncoder R5: register-resident warp-per-state; f32x2-packed stage A+B,
// vectorized L1-layout load, Walsh-tree Z expectations, setup-kernel tables.
// Layouts over amp index i[9:0] (qubit q <-> bit p=9-q):
//   L1: lane=i[9:5], reg j=i[4:0]     L0: lane=i[4:0], reg j=i[9:5]
// Pipeline:
//   load+norm (L1, real, packed) -> A gates q9..5 (L1 reg bits, f32x2)
//   -> T_A (L1->L0) -> A gates q4..0 (L0, f32x2) -> C1 gather+phaseA (->L1 cplx)
//   -> B gates q9..5 (L1, f32x2 cplx) -> T_B (L1->L0) -> B gates q4..0
//   -> C2 gather+phaseB (->L0, unpack) -> expvals, stage-C RY folded; q6-9 traced.
// CNOT-ring composite: new[i] = old[g(i)], g(i)=(i^(i>>1))^((i&1)?0x300:0).

constexpr int SPB = 4;               // states (warps) per block
constexpr int NT  = 32 * SPB;
using u64 = unsigned long long;

// flat tables: [0,64)=FA [64,128)=GA [128,192)=FB [192,256)=GB [256,276)=gAB [276,282)=gC
__device__ float2 d_tab[282];

__device__ __forceinline__ u64 pk2(float a, float b) {
    u64 r; asm("mov.b64 %0,{%1,%2};" : "=l"(r) : "f"(a), "f"(b)); return r;
}
__device__ __forceinline__ void upk2(u64 v, float& a, float& b) {
    asm("mov.b64 {%0,%1},%2;" : "=f"(a), "=f"(b) : "l"(v));
}
__device__ __forceinline__ u64 mul2(u64 a, u64 b) {
    u64 d; asm("mul.rn.f32x2 %0,%1,%2;" : "=l"(d) : "l"(a), "l"(b)); return d;
}
__device__ __forceinline__ u64 fma2(u64 a, u64 b, u64 c) {
    u64 d; asm("fma.rn.f32x2 %0,%1,%2,%3;" : "=l"(d) : "l"(a), "l"(b), "l"(c)); return d;
}
__device__ __forceinline__ float wsum(float v) {
#pragma unroll
    for (int o = 16; o; o >>= 1) v += __shfl_xor_sync(0xffffffffu, v, o);
    return v;
}

// ---- setup: build all tables once ------------------------------------------
__global__ void qae_setup(const float* __restrict__ w)
{
    int tid = threadIdx.x;
    if (tid < 256) {
        int tab = tid >> 6, t = tid & 63;
        int hi = t >> 1, lo = t & 1;
        int base = (tab >= 2) ? 40 : 10;
        float ph;
        if ((tab & 1) == 0) {   // F: keyed by i[9:5] (hi) and i0 (lo)
            int j = hi;
            int m5 = (j ^ (j >> 1)) & 1;
            int m6 = ((j >> 1) ^ (j >> 2)) & 1;
            int m7 = ((j >> 2) ^ (j >> 3)) & 1;
            int m8 = ((j >> 3) ^ (j >> 4) ^ lo) & 1;
            int m9 = ((j >> 4) ^ lo) & 1;
            ph  = w[base + 4] * (m5 ? 0.5f : -0.5f);
            ph += w[base + 3] * (m6 ? 0.5f : -0.5f);
            ph += w[base + 2] * (m7 ? 0.5f : -0.5f);
            ph += w[base + 1] * (m8 ? 0.5f : -0.5f);
            ph += w[base + 0] * (m9 ? 0.5f : -0.5f);
        } else {                // G: keyed by i[4:0] (hi) and i5 (lo)
            int l = hi;
            int m0 = (l ^ (l >> 1)) & 1;
            int m1 = ((l >> 1) ^ (l >> 2)) & 1;
            int m2 = ((l >> 2) ^ (l >> 3)) & 1;
            int m3 = ((l >> 3) ^ (l >> 4)) & 1;
            int m4 = ((l >> 4) ^ lo) & 1;
            ph  = w[base + 9] * (m0 ? 0.5f : -0.5f);
            ph += w[base + 8] * (m1 ? 0.5f : -0.5f);
            ph += w[base + 7] * (m2 ? 0.5f : -0.5f);
            ph += w[base + 6] * (m3 ? 0.5f : -0.5f);
            ph += w[base + 5] * (m4 ? 0.5f : -0.5f);
        }
        float c, s; sincosf(ph, &s, &c);
        d_tab[tid] = make_float2(c, s);
    } else if (tid < 276) {
        int e = tid - 256;
        int st = e / 10, q = e % 10;
        float th = st ? (w[20 + q] + w[30 + q]) : w[q];
        float c, s; sincosf(0.5f * th, &s, &c);
        d_tab[tid] = make_float2(c, s);
    } else if (tid < 282) {
        float c, s; sincosf(w[50 + (tid - 276)], &s, &c);
        d_tab[tid] = make_float2(c, s);
    }
}

__global__ void __launch_bounds__(NT)
qae5_kernel(const float* __restrict__ x,
            float* __restrict__ out,
            int B, int D)
{
    __shared__ u64    sbuf[SPB][33 * 32];   // staging (float view stride 34 / u64 stride 33)
    __shared__ float2 stab[282];

    const int tid  = threadIdx.x;
    const int wid  = tid >> 5;
    const int lane = tid & 31;
    const int b    = blockIdx.x * SPB + wid;

    for (int e = tid; e < 282; e += NT) stab[e] = d_tab[e];
    __syncthreads();
    if (b >= B) return;                 // whole-warp exit; rest is warp-local

    const float2* FA  = stab;
    const float2* GA  = stab + 64;
    const float2* FB  = stab + 128;
    const float2* GB  = stab + 192;
    const float2* gAB = stab + 256;
    const float2* gC  = stab + 276;

    float* bufr = (float*)sbuf[wid];    // stride-34 float view (stage A / C1)
    u64*   bufu = sbuf[wid];            // stride-33 u64 view   (T_B / C2)

    // ---- load + normalize (L1, real, packed over j-bit0 = qubit-9 pairs) ---
    u64 PA[16];
    float ss = 0.0f;
    const float* xrow = x + (size_t)b * D + lane * 32;
#pragma unroll
    for (int t = 0; t < 8; t++) {
        int idx = lane * 32 + t * 4;
        float4 v;
        if (idx + 3 < D) {
            v = *(const float4*)(xrow + t * 4);
        } else {
            v.x = (idx     < D) ? xrow[t * 4]     : 0.0f;
            v.y = (idx + 1 < D) ? xrow[t * 4 + 1] : 0.0f;
            v.z = (idx + 2 < D) ? xrow[t * 4 + 2] : 0.0f;
            v.w = (idx + 3 < D) ? xrow[t * 4 + 3] : 0.0f;
        }
        PA[2 * t]     = pk2(v.x, v.y);
        PA[2 * t + 1] = pk2(v.z, v.w);
        ss += v.x * v.x + v.y * v.y + v.z * v.z + v.w * v.w;
    }
    ss = wsum(ss);
    float inv = 1.0f / fmaxf(sqrtf(ss), 1e-8f);
    {
        u64 invp = pk2(inv, inv);
#pragma unroll
        for (int k = 0; k < 16; k++) PA[k] = mul2(PA[k], invp);
    }

    // ---- stage A, qubits 9..5 (L1 reg bits 0..4; bit0 in-pack) -------------
    {   // qubit 9 (in-pack)
        float2 g = gAB[9];
        u64 cc = pk2(g.x, g.x), ns = pk2(-g.y, g.y);
#pragma unroll
        for (int k = 0; k < 16; k++) {
            u64 t = mul2(PA[k], cc);
            float lo, hi; upk2(PA[k], lo, hi);
            PA[k] = fma2(pk2(hi, lo), ns, t);
        }
    }
#pragma unroll
    for (int p = 1; p < 5; p++) {       // qubit 9-p, pack-index bit p-1
        float2 g = gAB[9 - p];
        u64 cc = pk2(g.x, g.x), sp = pk2(g.y, g.y), sn = pk2(-g.y, -g.y);
        int m = 1 << (p - 1);
#pragma unroll
        for (int k = 0; k < 16; k++) if (!(k & m)) {
            u64 a = PA[k], bb = PA[k | m];
            PA[k]     = fma2(bb, sn, mul2(a, cc));
            PA[k | m] = fma2(a, sp, mul2(bb, cc));
        }
    }

    // ---- T_A: L1 -> L0. buffer addr(i) = i[9:5]*34 + i[4:0] ----------------
#pragma unroll
    for (int k = 0; k < 16; k++) bufu[lane * 17 + k] = PA[k];  // = floats lane*34+2k,2k+1
    __syncwarp();
    u64 PB[16];                         // L0, packed over j'-bit0 = i5 = qubit-4 pairs
#pragma unroll
    for (int k = 0; k < 16; k++)
        PB[k] = pk2(bufr[(2 * k) * 34 + lane], bufr[(2 * k + 1) * 34 + lane]);
    __syncwarp();

    // ---- stage A, qubits 4..0 (L0 reg bits; bit0 in-pack) ------------------
    {   // qubit 4 (in-pack)
        float2 g = gAB[4];
        u64 cc = pk2(g.x, g.x), ns = pk2(-g.y, g.y);
#pragma unroll
        for (int k = 0; k < 16; k++) {
            u64 t = mul2(PB[k], cc);
            float lo, hi; upk2(PB[k], lo, hi);
            PB[k] = fma2(pk2(hi, lo), ns, t);
        }
    }
#pragma unroll
    for (int p = 1; p < 5; p++) {       // qubit 4-p, pack-index bit p-1
        float2 g = gAB[4 - p];
        u64 cc = pk2(g.x, g.x), sp = pk2(g.y, g.y), sn = pk2(-g.y, -g.y);
        int m = 1 << (p - 1);
#pragma unroll
        for (int k = 0; k < 16; k++) if (!(k & m)) {
            u64 a = PB[k], bb = PB[k | m];
            PB[k]     = fma2(bb, sn, mul2(a, cc));
            PB[k | m] = fma2(a, sp, mul2(bb, cc));
        }
    }

    // ---- C1: CNOT gather + phase A (store L0 regs, read into L1, -> cplx) --
    u64 P[32];
    {
#pragma unroll
        for (int k = 0; k < 16; k++) {  // addr(i) = i[9:5]*34 + i[4:0]; j'=2k,2k+1
            float lo, hi; upk2(PB[k], lo, hi);
            bufr[(2 * k) * 34 + lane]     = lo;
            bufr[(2 * k + 1) * 34 + lane] = hi;
        }
        __syncwarp();
        float2 f0 = FA[lane * 2], f1 = FA[lane * 2 + 1];
#pragma unroll
        for (int j = 0; j < 32; j++) {  // output L1: lane=i[9:5], j=i[4:0]
            int i  = (lane << 5) | j;
            int gi = (i ^ (i >> 1)) ^ ((j & 1) ? 0x300 : 0);
            float r = bufr[(gi >> 5) * 34 + (gi & 31)];
            float2 f = (j & 1) ? f1 : f0;
            float2 g = GA[j * 2 + (lane & 1)];
            float pr = f.x * g.x - f.y * g.y;
            float pi = f.x * g.y + f.y * g.x;
            P[j] = mul2(pk2(r, r), pk2(pr, pi));
        }
        __syncwarp();
    }

    // ---- stage B, qubits 9..5 (L1 reg bits, complex f32x2) -----------------
#pragma unroll
    for (int bl = 0; bl < 5; bl++) {
        float2 g = gAB[10 + 9 - bl];
        u64 cc = pk2(g.x, g.x), sp = pk2(g.y, g.y), sn = pk2(-g.y, -g.y);
        int m = 1 << bl;
#pragma unroll
        for (int j = 0; j < 32; j++) if (!(j & m)) {
            u64 a = P[j], bb = P[j | m];
            P[j]     = fma2(bb, sn, mul2(a, cc));
            P[j | m] = fma2(a, sp, mul2(bb, cc));
        }
    }

    // ---- T_B: L1 -> L0 (u64 transpose, stride 33) --------------------------
#pragma unroll
    for (int j = 0; j < 32; j++) bufu[lane * 33 + j] = P[j];
    __syncwarp();
#pragma unroll
    for (int j = 0; j < 32; j++) P[j] = bufu[j * 33 + lane];
    __syncwarp();

    // ---- stage B, qubits 4..0 (L0 reg bits) --------------------------------
#pragma unroll
    for (int bl = 0; bl < 5; bl++) {
        float2 g = gAB[10 + 4 - bl];
        u64 cc = pk2(g.x, g.x), sp = pk2(g.y, g.y), sn = pk2(-g.y, -g.y);
        int m = 1 << bl;
#pragma unroll
        for (int j = 0; j < 32; j++) if (!(j & m)) {
            u64 a = P[j], bb = P[j | m];
            P[j]     = fma2(bb, sn, mul2(a, cc));
            P[j | m] = fma2(a, sp, mul2(bb, cc));
        }
    }

    // ---- C2: CNOT gather + phase B (L0 -> L0, unpack to X,Y) ---------------
    float X[32], Y[32];
    {
#pragma unroll
        for (int j = 0; j < 32; j++) bufu[lane * 33 + j] = P[j]; // addr(i)=i[4:0]*33+i[9:5]
        __syncwarp();
        float2 g0 = GB[lane * 2], g1 = GB[lane * 2 + 1];
#pragma unroll
        for (int j = 0; j < 32; j++) {  // output L0: lane=i[4:0], j=i[9:5]
            int i  = (j << 5) | lane;
            int gi = (i ^ (i >> 1)) ^ ((lane & 1) ? 0x300 : 0);
            u64 v = bufu[(gi & 31) * 33 + (gi >> 5)];
            float vx, vy; upk2(v, vx, vy);
            float2 f = FB[j * 2 + (lane & 1)];
            float2 g = (j & 1) ? g1 : g0;
            float pr = f.x * g.x - f.y * g.y;
            float pi = f.x * g.y + f.y * g.x;
            X[j] = vx * pr - vy * pi;
            Y[j] = vx * pi + vy * pr;
        }
    }

    // ---- Z expectations via partial Walsh tree -----------------------------
    float zq[6];
    {
        float s0[16]; float z4 = 0.0f;
#pragma unroll
        for (int k = 0; k < 16; k++) {
            float a  = X[2 * k] * X[2 * k] + Y[2 * k] * Y[2 * k];
            float bq = X[2 * k + 1] * X[2 * k + 1] + Y[2 * k + 1] * Y[2 * k + 1];
            s0[k] = a + bq;  z4 += a - bq;
        }
        float s1[8]; float z3 = 0.0f;
#pragma unroll
        for (int k = 0; k < 8; k++) { s1[k] = s0[2 * k] + s0[2 * k + 1]; z3 += s0[2 * k] - s0[2 * k + 1]; }
        float s2[4]; float z2 = 0.0f;
#pragma unroll
        for (int k = 0; k < 4; k++) { s2[k] = s1[2 * k] + s1[2 * k + 1]; z2 += s1[2 * k] - s1[2 * k + 1]; }
        float s3[2]; float z1 = 0.0f;
#pragma unroll
        for (int k = 0; k < 2; k++) { s3[k] = s2[2 * k] + s2[2 * k + 1]; z1 += s2[2 * k] - s2[2 * k + 1]; }
        zq[0] = s3[0] - s3[1];
        zq[1] = z1; zq[2] = z2; zq[3] = z3; zq[4] = z4;
        float tot = s3[0] + s3[1];
        zq[5] = (lane & 16) ? -tot : tot;
    }

    // ---- X/Y expectations ---------------------------------------------------
    float xr[6], yi[6];
#pragma unroll
    for (int q = 0; q < 5; q++) {               // measured qubits 0..4 (j bits)
        int m = 1 << (4 - q);
        float xa = 0.0f, ya = 0.0f;
#pragma unroll
        for (int j = 0; j < 32; j++) if (!(j & m)) {
            float ax = X[j], ay = Y[j], bx = X[j | m], by = Y[j | m];
            xa += ax * bx + ay * by;
            ya += ax * by - ay * bx;
        }
        xr[q] = 2.0f * xa;
        yi[q] = 2.0f * ya;
    }
    {                                            // qubit 5 = lane bit 4
        float x5 = 0.0f, y5 = 0.0f;
#pragma unroll
        for (int j = 0; j < 32; j++) {
            float px = __shfl_xor_sync(0xffffffffu, X[j], 16);
            float py = __shfl_xor_sync(0xffffffffu, Y[j], 16);
            x5 += X[j] * px + Y[j] * py;
            y5 += X[j] * py - Y[j] * px;
        }
        if (lane & 16) y5 = -y5;
        xr[5] = x5;
        yi[5] = y5;
    }

#pragma unroll
    for (int q = 0; q < 6; q++) {
        xr[q] = wsum(xr[q]);
        yi[q] = wsum(yi[q]);
        zq[q] = wsum(zq[q]);
    }

    if (lane == 0) {
        float* o = out + (size_t)b * 18;
#pragma unroll
        for (int q = 0; q < 6; q++) {
            float c = gC[q].x, s = gC[q].y;
            o[q]      = c * xr[q] + s * zq[q];
            o[6 + q]  = yi[q];
            o[12 + q] = c * zq[q] - s * xr[q];
        }
    }
}

extern "C" void kernel_launch(void* const* d_in, const int* in_sizes, int n_in,
                              void* d_out, int out_size)
{
    int ix = 0, iw = 1;
    if (n_in >= 2 && in_sizes[0] < in_sizes[1]) { ix = 1; iw = 0; }
    const float* x = (const float*)d_in[ix];
    const float* w = (const float*)d_in[iw];
    float* out = (float*)d_out;

    int B = out_size / 18;
    int D = (B > 0) ? (in_sizes[ix] / B) : 0;

    qae_setup<<<1, 288>>>(w);
    int grid = (B + SPB - 1) / SPB;
    qae5_kernel<<<grid, NT>>>(x, out, B, D);
}

// round 6
// speedup vs baseline: 4.7717x; 1.1067x over previous
#include <cuda_runtime.h>

// QAEEncoder R6: warp-per-state, f32x2-packed throughout, precomputed full
// phase tables (global, L2-resident), packed expectations, occupancy-forced.
// Layouts over amp index i[9:0] (qubit q <-> bit p=9-q):
//   L1: lane=i[9:5], reg j=i[4:0]     L0: lane=i[4:0], reg j=i[9:5]
// Pipeline:
//   load+norm (L1, real, packed) -> A gates q9..5 (L1 reg bits, f32x2)
//   -> T_A (L1->L0) -> A gates q4..0 (L0, f32x2) -> C1 gather+PhA (->L1 cplx)
//   -> B gates q9..5 (L1) -> T_B (L1->L0) -> B gates q4..0
//   -> C2 gather+PhB (stay packed) -> packed expvals, stage-C RY folded;
//   qubits 6-9 traced out (cannot affect measured reduced state).
// CNOT-ring composite: new[i] = old[g(i)], g(i)=(i^(i>>1))^((i&1)?0x300:0).

constexpr int SPB = 4;               // states (warps) per block
constexpr int NT  = 32 * SPB;
using u64 = unsigned long long;

__device__ float2 d_phA[1024];   // transposed: entry for dest i at [(i&31)*32 + (i>>5)]
__device__ float2 d_phB[1024];   // natural:   entry for dest i at [i]
__device__ float2 d_g[26];       // [0,20)=gAB half-angle, [20,26)=gC full-angle

__device__ __forceinline__ u64 pk2(float a, float b) {
    u64 r; asm("mov.b64 %0,{%1,%2};" : "=l"(r) : "f"(a), "f"(b)); return r;
}
__device__ __forceinline__ void upk2(u64 v, float& a, float& b) {
    asm("mov.b64 {%0,%1},%2;" : "=f"(a), "=f"(b) : "l"(v));
}
__device__ __forceinline__ u64 mul2(u64 a, u64 b) {
    u64 d; asm("mul.rn.f32x2 %0,%1,%2;" : "=l"(d) : "l"(a), "l"(b)); return d;
}
__device__ __forceinline__ u64 fma2(u64 a, u64 b, u64 c) {
    u64 d; asm("fma.rn.f32x2 %0,%1,%2,%3;" : "=l"(d) : "l"(a), "l"(b), "l"(c)); return d;
}
__device__ __forceinline__ float wsum(float v) {
#pragma unroll
    for (int o = 16; o; o >>= 1) v += __shfl_xor_sync(0xffffffffu, v, o);
    return v;
}

// ---- setup: full phase tables + gate angles --------------------------------
__global__ void qae_setup(const float* __restrict__ w)
{
    int t = threadIdx.x;   // 1024 threads
    {
        int gi = (t ^ (t >> 1)) ^ ((t & 1) ? 0x300 : 0);
        float phA = 0.0f, phB = 0.0f;
#pragma unroll
        for (int p = 0; p < 10; p++) {
            float sgn = (gi >> p) & 1 ? 0.5f : -0.5f;
            phA += w[10 + 9 - p] * sgn;
            phB += w[40 + 9 - p] * sgn;
        }
        float c, s;
        sincosf(phA, &s, &c);
        d_phA[(t & 31) * 32 + (t >> 5)] = make_float2(c, s);
        sincosf(phB, &s, &c);
        d_phB[t] = make_float2(c, s);
    }
    if (t < 20) {
        int st = t / 10, q = t % 10;
        float th = st ? (w[20 + q] + w[30 + q]) : w[q];
        float c, s; sincosf(0.5f * th, &s, &c);
        d_g[t] = make_float2(c, s);
    } else if (t < 26) {
        float c, s; sincosf(w[50 + (t - 20)], &s, &c);
        d_g[t] = make_float2(c, s);
    }
}

__global__ void __launch_bounds__(NT, 6)
qae6_kernel(const float* __restrict__ x,
            float* __restrict__ out,
            int B, int D)
{
    __shared__ u64    sbuf[SPB][33 * 32];   // staging: float view stride 34, u64 stride 33
    __shared__ float2 stab[26];

    const int tid  = threadIdx.x;
    const int wid  = tid >> 5;
    const int lane = tid & 31;
    const int b    = blockIdx.x * SPB + wid;

    if (tid < 26) stab[tid] = d_g[tid];
    __syncthreads();
    if (b >= B) return;                 // whole-warp exit; rest is warp-local

    const float2* gAB = stab;
    const float2* gC  = stab + 20;

    float* bufr = (float*)sbuf[wid];    // stride-34 float view (T_A / C1)
    u64*   bufu = sbuf[wid];            // stride-33 u64 view   (T_B / C2)

    // ---- load + normalize (L1, real, packed over j-bit0 = qubit-9 pairs) ---
    u64 PA[16];
    float ss = 0.0f;
    const float* xrow = x + (size_t)b * D + lane * 32;
#pragma unroll
    for (int t = 0; t < 8; t++) {
        int idx = lane * 32 + t * 4;
        float4 v;
        if (idx + 3 < D) {
            v = *(const float4*)(xrow + t * 4);
        } else {
            v.x = (idx     < D) ? xrow[t * 4]     : 0.0f;
            v.y = (idx + 1 < D) ? xrow[t * 4 + 1] : 0.0f;
            v.z = (idx + 2 < D) ? xrow[t * 4 + 2] : 0.0f;
            v.w = (idx + 3 < D) ? xrow[t * 4 + 3] : 0.0f;
        }
        PA[2 * t]     = pk2(v.x, v.y);
        PA[2 * t + 1] = pk2(v.z, v.w);
        ss += v.x * v.x + v.y * v.y + v.z * v.z + v.w * v.w;
    }
    ss = wsum(ss);
    float inv = 1.0f / fmaxf(sqrtf(ss), 1e-8f);
    {
        u64 invp = pk2(inv, inv);
#pragma unroll
        for (int k = 0; k < 16; k++) PA[k] = mul2(PA[k], invp);
    }

    // ---- stage A, qubits 9..5 (L1 reg bits; qubit 9 in-pack) ---------------
    {
        float2 g = gAB[9];
        u64 cc = pk2(g.x, g.x), ns = pk2(-g.y, g.y);
#pragma unroll
        for (int k = 0; k < 16; k++) {
            u64 t = mul2(PA[k], cc);
            float lo, hi; upk2(PA[k], lo, hi);
            PA[k] = fma2(pk2(hi, lo), ns, t);
        }
    }
#pragma unroll
    for (int p = 1; p < 5; p++) {
        float2 g = gAB[9 - p];
        u64 cc = pk2(g.x, g.x), sp = pk2(g.y, g.y), sn = pk2(-g.y, -g.y);
        int m = 1 << (p - 1);
#pragma unroll
        for (int k = 0; k < 16; k++) if (!(k & m)) {
            u64 a = PA[k], bb = PA[k | m];
            PA[k]     = fma2(bb, sn, mul2(a, cc));
            PA[k | m] = fma2(a, sp, mul2(bb, cc));
        }
    }

    // ---- T_A: L1 -> L0. buffer addr(i) = i[9:5]*34 + i[4:0] ----------------
#pragma unroll
    for (int k = 0; k < 16; k++) bufu[lane * 17 + k] = PA[k];
    __syncwarp();
    u64 PB[16];                         // L0, packed over i5 = qubit-4 pairs
#pragma unroll
    for (int k = 0; k < 16; k++)
        PB[k] = pk2(bufr[(2 * k) * 34 + lane], bufr[(2 * k + 1) * 34 + lane]);
    __syncwarp();

    // ---- stage A, qubits 4..0 (L0 reg bits; qubit 4 in-pack) ---------------
    {
        float2 g = gAB[4];
        u64 cc = pk2(g.x, g.x), ns = pk2(-g.y, g.y);
#pragma unroll
        for (int k = 0; k < 16; k++) {
            u64 t = mul2(PB[k], cc);
            float lo, hi; upk2(PB[k], lo, hi);
            PB[k] = fma2(pk2(hi, lo), ns, t);
        }
    }
#pragma unroll
    for (int p = 1; p < 5; p++) {
        float2 g = gAB[4 - p];
        u64 cc = pk2(g.x, g.x), sp = pk2(g.y, g.y), sn = pk2(-g.y, -g.y);
        int m = 1 << (p - 1);
#pragma unroll
        for (int k = 0; k < 16; k++) if (!(k & m)) {
            u64 a = PB[k], bb = PB[k | m];
            PB[k]     = fma2(bb, sn, mul2(a, cc));
            PB[k | m] = fma2(a, sp, mul2(bb, cc));
        }
    }

    // ---- C1: CNOT gather + PhA (store L0, read into L1, -> complex) --------
    u64 P[32];
    {
#pragma unroll
        for (int k = 0; k < 16; k++) {
            float lo, hi; upk2(PB[k], lo, hi);
            bufr[(2 * k) * 34 + lane]     = lo;
            bufr[(2 * k + 1) * 34 + lane] = hi;
        }
        __syncwarp();
        const u64* phA = (const u64*)d_phA;
#pragma unroll
        for (int j = 0; j < 32; j++) {  // output L1: lane=i[9:5], j=i[4:0]
            int i  = (lane << 5) | j;
            int gi = (i ^ (i >> 1)) ^ ((j & 1) ? 0x300 : 0);
            float r = bufr[(gi >> 5) * 34 + (gi & 31)];
            u64 ph = __ldg(&phA[j * 32 + lane]);   // transposed: coalesced
            P[j] = mul2(pk2(r, r), ph);
        }
        __syncwarp();
    }

    // ---- stage B, qubits 9..5 (L1 reg bits, complex f32x2) -----------------
#pragma unroll
    for (int bl = 0; bl < 5; bl++) {
        float2 g = gAB[10 + 9 - bl];
        u64 cc = pk2(g.x, g.x), sp = pk2(g.y, g.y), sn = pk2(-g.y, -g.y);
        int m = 1 << bl;
#pragma unroll
        for (int j = 0; j < 32; j++) if (!(j & m)) {
            u64 a = P[j], bb = P[j | m];
            P[j]     = fma2(bb, sn, mul2(a, cc));
            P[j | m] = fma2(a, sp, mul2(bb, cc));
        }
    }

    // ---- T_B: L1 -> L0 (u64 transpose, stride 33) --------------------------
#pragma unroll
    for (int j = 0; j < 32; j++) bufu[lane * 33 + j] = P[j];
    __syncwarp();
#pragma unroll
    for (int j = 0; j < 32; j++) P[j] = bufu[j * 33 + lane];
    __syncwarp();

    // ---- stage B, qubits 4..0 (L0 reg bits) --------------------------------
#pragma unroll
    for (int bl = 0; bl < 5; bl++) {
        float2 g = gAB[10 + 4 - bl];
        u64 cc = pk2(g.x, g.x), sp = pk2(g.y, g.y), sn = pk2(-g.y, -g.y);
        int m = 1 << bl;
#pragma unroll
        for (int j = 0; j < 32; j++) if (!(j & m)) {
            u64 a = P[j], bb = P[j | m];
            P[j]     = fma2(bb, sn, mul2(a, cc));
            P[j | m] = fma2(a, sp, mul2(bb, cc));
        }
    }

    // ---- C2: CNOT gather + PhB (L0 -> L0, stay packed) ---------------------
    {
#pragma unroll
        for (int j = 0; j < 32; j++) bufu[lane * 33 + j] = P[j]; // addr(i)=i[4:0]*33+i[9:5]
        __syncwarp();
        const u64* phB = (const u64*)d_phB;
#pragma unroll
        for (int j = 0; j < 32; j++) {  // output L0: lane=i[4:0], j=i[9:5]
            int i  = (j << 5) | lane;
            int gi = (i ^ (i >> 1)) ^ ((lane & 1) ? 0x300 : 0);
            u64 v = bufu[(gi & 31) * 33 + (gi >> 5)];
            u64 ph = __ldg(&phB[i]);                // natural: coalesced
            float vx, vy, pr, pi;
            upk2(v, vx, vy); upk2(ph, pr, pi);
            P[j] = pk2(vx * pr - vy * pi, vx * pi + vy * pr);
        }
    }

    // ---- Z expectations via partial Walsh tree (packed squares) ------------
    float zq[6];
    {
        float s0[16]; float z4 = 0.0f;
#pragma unroll
        for (int k = 0; k < 16; k++) {
            u64 sa = mul2(P[2 * k], P[2 * k]);
            u64 sb = mul2(P[2 * k + 1], P[2 * k + 1]);
            float al, ah, bl, bh; upk2(sa, al, ah); upk2(sb, bl, bh);
            float a = al + ah, bq = bl + bh;
            s0[k] = a + bq;  z4 += a - bq;
        }
        float s1[8]; float z3 = 0.0f;
#pragma unroll
        for (int k = 0; k < 8; k++) { s1[k] = s0[2 * k] + s0[2 * k + 1]; z3 += s0[2 * k] - s0[2 * k + 1]; }
        float s2[4]; float z2 = 0.0f;
#pragma unroll
        for (int k = 0; k < 4; k++) { s2[k] = s1[2 * k] + s1[2 * k + 1]; z2 += s1[2 * k] - s1[2 * k + 1]; }
        float s3[2]; float z1 = 0.0f;
#pragma unroll
        for (int k = 0; k < 2; k++) { s3[k] = s2[2 * k] + s2[2 * k + 1]; z1 += s2[2 * k] - s2[2 * k + 1]; }
        zq[0] = s3[0] - s3[1];
        zq[1] = z1; zq[2] = z2; zq[3] = z3; zq[4] = z4;
        float tot = s3[0] + s3[1];
        zq[5] = (lane & 16) ? -tot : tot;
    }

    // ---- X/Y expectations (packed accumulators) ----------------------------
    float xr[6], yi[6];
#pragma unroll
    for (int q = 0; q < 5; q++) {               // measured qubits 0..4 (j bits)
        int m = 1 << (4 - q);
        u64 acd = 0ull, acc = 0ull;             // bits of (0.0f,0.0f)
#pragma unroll
        for (int j = 0; j < 32; j++) if (!(j & m)) {
            u64 a = P[j], bp = P[j | m];
            acd = fma2(a, bp, acd);             // (Σ ax*bx, Σ ay*by)
            float bl, bh; upk2(bp, bl, bh);
            acc = fma2(a, pk2(bh, bl), acc);    // (Σ ax*by, Σ ay*bx)
        }
        float dl, dh, cl, ch; upk2(acd, dl, dh); upk2(acc, cl, ch);
        xr[q] = 2.0f * (dl + dh);
        yi[q] = 2.0f * (cl - ch);
    }
    {                                            // qubit 5 = lane bit 4
        u64 acd = 0ull, acc = 0ull;
#pragma unroll
        for (int j = 0; j < 32; j++) {
            u64 p = __shfl_xor_sync(0xffffffffu, P[j], 16);
            acd = fma2(P[j], p, acd);
            float pl, ph; upk2(p, pl, ph);
            acc = fma2(P[j], pk2(ph, pl), acc);
        }
        float dl, dh, cl, ch; upk2(acd, dl, dh); upk2(acc, cl, ch);
        float y5 = cl - ch;
        if (lane & 16) y5 = -y5;
        xr[5] = dl + dh;                         // counts both halves already
        yi[5] = y5;
    }

#pragma unroll
    for (int q = 0; q < 6; q++) {
        xr[q] = wsum(xr[q]);
        yi[q] = wsum(yi[q]);
        zq[q] = wsum(zq[q]);
    }

    if (lane == 0) {
        float* o = out + (size_t)b * 18;
#pragma unroll
        for (int q = 0; q < 6; q++) {
            float c = gC[q].x, s = gC[q].y;
            o[q]      = c * xr[q] + s * zq[q];
            o[6 + q]  = yi[q];
            o[12 + q] = c * zq[q] - s * xr[q];
        }
    }
}

extern "C" void kernel_launch(void* const* d_in, const int* in_sizes, int n_in,
                              void* d_out, int out_size)
{
    int ix = 0, iw = 1;
    if (n_in >= 2 && in_sizes[0] < in_sizes[1]) { ix = 1; iw = 0; }
    const float* x = (const float*)d_in[ix];
    const float* w = (const float*)d_in[iw];
    float* out = (float*)d_out;

    int B = out_size / 18;
    int D = (B > 0) ? (in_sizes[ix] / B) : 0;

    qae_setup<<<1, 1024>>>(w);
    int grid = (B + SPB - 1) / SPB;
    qae6_kernel<<<grid, NT>>>(x, out, B, D);
}